// round 16
// baseline (speedup 1.0000x reference)
#include <cuda_runtime.h>
#include <cuda_fp16.h>

#define NUM_PL 50000
#define NUM_TR 100000
#define NUM_AR 10000
#define OFF_TR NUM_PL
#define OFF_AR (NUM_PL + NUM_TR)
#define NTOT   (NUM_PL + NUM_TR + NUM_AR)
#define HID    64
#define MAXDEG 96             // fixed adjacency stride; true max deg ~70
#define SPLIT  96000          // pipeline split (divisible by 64)

typedef unsigned long long ull;

// -------- scratch (device globals; no runtime allocation) --------
__device__ __align__(16) __half g_h0  [(size_t)NTOT * HID];
__device__ __align__(16) __half g_h1  [(size_t)NTOT * HID];
__device__ __align__(16) __half g_aggh[(size_t)NTOT * HID];
__device__ __align__(16) __half g_wh  [2 * 64 * 128];
__device__ int g_deg[NTOT];
__device__ __align__(16) int g_adj[(size_t)NTOT * MAXDEG + 16]; // pad for prefetch over-read

// -------- helpers --------
__device__ __forceinline__ ull dup_f32(float x) {
    ull r; asm("mov.b64 %0, {%1,%1};" : "=l"(r) : "f"(x)); return r;
}
__device__ __forceinline__ void ffma2(ull& d, ull a, ull b) {
    asm("fma.rn.f32x2 %0, %1, %2, %3;" : "=l"(d) : "l"(a), "l"(b), "l"(d));
}
__device__ __forceinline__ float2 unpack2(ull v) {
    float2 f; asm("mov.b64 {%0,%1}, %2;" : "=f"(f.x), "=f"(f.y) : "l"(v)); return f;
}
__device__ __forceinline__ float2 h2f(unsigned u) {
    return __half22float2(*(const __half2*)&u);
}
__device__ __forceinline__ __half2 u2h(unsigned u) {
    return *(const __half2*)&u;
}
__device__ __forceinline__ unsigned f2h2(float a, float b) {
    __half2 h = __floats2half2_rn(a, b);
    return *(const unsigned*)&h;
}
__device__ __forceinline__ void mma_f16(float* c, unsigned a0, unsigned a1,
                                        unsigned a2, unsigned a3,
                                        unsigned b0, unsigned b1) {
    asm volatile("mma.sync.aligned.m16n8k16.row.col.f32.f16.f16.f32 "
                 "{%0,%1,%2,%3}, {%4,%5,%6,%7}, {%8,%9}, {%0,%1,%2,%3};"
                 : "+f"(c[0]), "+f"(c[1]), "+f"(c[2]), "+f"(c[3])
                 : "r"(a0), "r"(a1), "r"(a2), "r"(a3), "r"(b0), "r"(b1));
}

// process one 4-neighbor group (uint2 slices) into acc[4] — HADD2 tree
__device__ __forceinline__ void acc_group2(const uint2& v0, const uint2& v1,
                                           const uint2& v2, const uint2& v3,
                                           float* acc) {
#pragma unroll
    for (int q = 0; q < 2; q++) {
        __half2 sh = __hadd2(__hadd2(u2h((&v0.x)[q]), u2h((&v1.x)[q])),
                             __hadd2(u2h((&v2.x)[q]), u2h((&v3.x)[q])));
        float2 f = __half22float2(sh);
        acc[q * 2 + 0] += f.x; acc[q * 2 + 1] += f.y;
    }
}

// -------- init playlist & artist rows (fp16) --------
__global__ void init_emb_kernel(const float* __restrict__ pl_emb,
                                const float* __restrict__ ar_emb,
                                const float* __restrict__ type_emb) {
    int t = blockIdx.x * blockDim.x + threadIdx.x;
    int total = (NUM_PL + NUM_AR) * (HID / 4);
    if (t >= total) return;
    int node = t >> 4;
    int c    = (t & 15) * 4;
    const float* src; const float* ty; size_t row;
    if (node < NUM_PL) {
        src = pl_emb + (size_t)node * HID;
        row = (size_t)node * HID;
        ty  = type_emb;
    } else {
        int a = node - NUM_PL;
        src = ar_emb + (size_t)a * HID;
        row = (size_t)(OFF_AR + a) * HID;
        ty  = type_emb + 2 * HID;
    }
    float4 v  = *(const float4*)(src + c);
    float4 tv = *(const float4*)(ty  + c);
    v.x += tv.x; v.y += tv.y; v.z += tv.z; v.w += tv.w;
    uint2 h; h.x = f2h2(v.x, v.y); h.y = f2h2(v.z, v.w);
    *(uint2*)(g_h0 + row + c) = h;
}

// -------- weight pre-convert --------
__global__ void wconv_kernel(const float* __restrict__ Wl,
                             const float* __restrict__ Wr) {
    int t = blockIdx.x * blockDim.x + threadIdx.x;
    if (t >= 2 * 64 * 128) return;
    int l = t >> 13;
    int o = (t >> 7) & 63;
    int k = t & 127;
    float v = (k < 64) ? Wl[l * 64 * 64 + o * 64 + k]
                       : Wr[l * 64 * 64 + o * 64 + (k - 64)];
    g_wh[t] = __float2half_rn(v);
}

__global__ void zero_deg_kernel() {
    int i = blockIdx.x * blockDim.x + threadIdx.x;
    if (i < NTOT) g_deg[i] = 0;
}

// -------- single-pass CSR build (atomic-throughput bound; at floor) --------
__global__ void fill_kernel(const int* __restrict__ s1, const int* __restrict__ d1, int n1,
                            const int* __restrict__ s2, const int* __restrict__ d2, int n2) {
    int base = (blockIdx.x * blockDim.x + threadIdx.x) * 4;
    int total = n1 + n2;
    int aa[4], bb[4];
    int cnt = 0;
#pragma unroll
    for (int u = 0; u < 4; u++) {
        int e = base + u;
        if (e < total) {
            if (e < n1) { aa[u] = __ldg(s1 + e);               bb[u] = __ldg(d1 + e) + OFF_TR; }
            else        { aa[u] = __ldg(s2 + e - n1) + OFF_TR; bb[u] = __ldg(d2 + e - n1) + OFF_AR; }
            cnt = u + 1;
        }
    }
#pragma unroll
    for (int u = 0; u < 4; u++) {
        if (u < cnt) {
            int pa = atomicAdd(&g_deg[aa[u]], 1);
            if (pa < MAXDEG) g_adj[(size_t)aa[u] * MAXDEG + pa] = bb[u];
            int pb = atomicAdd(&g_deg[bb[u]], 1);
            if (pb < MAXDEG) g_adj[(size_t)bb[u] * MAXDEG + pb] = aa[u];
        }
    }
}

// -------- gather: 16 lanes/node (8B slices); 8-wide stage + 4-wide pipelined + tail --------
__global__ void gather_kernel(int layer, int nodeStart, int nodeCount) {
    const __half* __restrict__ H = layer ? g_h1 : g_h0;
    int t = blockIdx.x * blockDim.x + threadIdx.x;
    int nrel = t >> 4;
    if (nrel >= nodeCount) return;
    int node = nodeStart + nrel;
    int c = (t & 15) * 4;          // 4 half-columns per lane
    const int* __restrict__ adj = g_adj + (size_t)node * MAXDEG;
    int d = g_deg[node];
    if (d > MAXDEG) d = MAXDEG;
    float acc[4];
#pragma unroll
    for (int j = 0; j < 4; j++) acc[j] = 0.f;

    // s always holds adj[i..i+3] (padded array -> safe over-read)
    int4 s = *(const int4*)(adj);
    int i = 0;

    // 8-wide stage: 8 independent 8B loads in flight per lane
    while (i + 8 <= d) {
        int4 sa = s;
        int4 sb = *(const int4*)(adj + i + 4);
        s = *(const int4*)(adj + i + 8);           // prefetch next group
        uint2 v0 = *(const uint2*)(H + (size_t)sa.x * HID + c);
        uint2 v1 = *(const uint2*)(H + (size_t)sa.y * HID + c);
        uint2 v2 = *(const uint2*)(H + (size_t)sa.z * HID + c);
        uint2 v3 = *(const uint2*)(H + (size_t)sa.w * HID + c);
        uint2 v4 = *(const uint2*)(H + (size_t)sb.x * HID + c);
        uint2 v5 = *(const uint2*)(H + (size_t)sb.y * HID + c);
        uint2 v6 = *(const uint2*)(H + (size_t)sb.z * HID + c);
        uint2 v7 = *(const uint2*)(H + (size_t)sb.w * HID + c);
        acc_group2(v0, v1, v2, v3, acc);
        acc_group2(v4, v5, v6, v7, acc);
        i += 8;
    }
    // 4-wide pipelined stage
    while (i + 4 <= d) {
        int4 sn = *(const int4*)(adj + i + 4);
        uint2 v0 = *(const uint2*)(H + (size_t)s.x * HID + c);
        uint2 v1 = *(const uint2*)(H + (size_t)s.y * HID + c);
        uint2 v2 = *(const uint2*)(H + (size_t)s.z * HID + c);
        uint2 v3 = *(const uint2*)(H + (size_t)s.w * HID + c);
        acc_group2(v0, v1, v2, v3, acc);
        s = sn;
        i += 4;
    }
    // tail (0..3): neighbors already in s
    int r = d - i;
    if (r > 0) {
        uint2 v = *(const uint2*)(H + (size_t)s.x * HID + c);
#pragma unroll
        for (int q = 0; q < 2; q++) {
            float2 f = h2f((&v.x)[q]);
            acc[q * 2 + 0] += f.x; acc[q * 2 + 1] += f.y;
        }
    }
    if (r > 1) {
        uint2 v = *(const uint2*)(H + (size_t)s.y * HID + c);
#pragma unroll
        for (int q = 0; q < 2; q++) {
            float2 f = h2f((&v.x)[q]);
            acc[q * 2 + 0] += f.x; acc[q * 2 + 1] += f.y;
        }
    }
    if (r > 2) {
        uint2 v = *(const uint2*)(H + (size_t)s.z * HID + c);
#pragma unroll
        for (int q = 0; q < 2; q++) {
            float2 f = h2f((&v.x)[q]);
            acc[q * 2 + 0] += f.x; acc[q * 2 + 1] += f.y;
        }
    }

    float rd = 1.0f / (float)(d > 0 ? d : 1);
    uint2 hv;
    hv.x = f2h2(acc[0] * rd, acc[1] * rd);
    hv.y = f2h2(acc[2] * rd, acc[3] * rd);
    *(uint2*)(g_aggh + (size_t)node * HID + c) = hv;
}

// -------- track GEMM (exact f32x2) --------
__global__ void __launch_bounds__(128) track_gemm_kernel(
        const float* __restrict__ A, const float* __restrict__ W,
        const float* __restrict__ bias, const float* __restrict__ bias2) {
    __shared__ float Ws[64][68];
    __shared__ float rows[128][36];
    const int tid = threadIdx.x;
    const int tx  = tid & 15;
    const int ty  = tid >> 4;
    const int nodeBase = blockIdx.x * 32;

    for (int it = 0; it < 32; it++)
        rows[tid][it] = A[(size_t)(nodeBase + it) * 128 + tid];

    ull a01[4], a23[4];
#pragma unroll
    for (int i = 0; i < 4; i++) { a01[i] = 0ull; a23[i] = 0ull; }

    for (int h = 0; h < 2; h++) {
        __syncthreads();
        for (int idx = tid; idx < 64 * 64; idx += 128) {
            int o = idx >> 6, k = idx & 63;
            Ws[k][o] = W[(size_t)o * 128 + h * 64 + k];
        }
        __syncthreads();
#pragma unroll 8
        for (int k = 0; k < 64; k++) {
            ulonglong2 rp = *(const ulonglong2*)&rows[(h << 6) + k][ty * 4];
            float4 w = *(const float4*)&Ws[k][tx * 4];
            ull w0 = dup_f32(w.x), w1 = dup_f32(w.y);
            ull w2 = dup_f32(w.z), w3 = dup_f32(w.w);
            ffma2(a01[0], rp.x, w0); ffma2(a23[0], rp.y, w0);
            ffma2(a01[1], rp.x, w1); ffma2(a23[1], rp.y, w1);
            ffma2(a01[2], rp.x, w2); ffma2(a23[2], rp.y, w2);
            ffma2(a01[3], rp.x, w3); ffma2(a23[3], rp.y, w3);
        }
    }

    const int o = tx * 4;
    float b0 = bias[o] + bias2[o],         b1 = bias[o + 1] + bias2[o + 1];
    float b2 = bias[o + 2] + bias2[o + 2], b3 = bias[o + 3] + bias2[o + 3];
    float res[4][4];
#pragma unroll
    for (int i = 0; i < 4; i++) {
        float2 p = unpack2(a01[i]);
        float2 q = unpack2(a23[i]);
        res[0][i] = p.x; res[1][i] = p.y; res[2][i] = q.x; res[3][i] = q.y;
    }
#pragma unroll
    for (int j = 0; j < 4; j++) {
        size_t row = (size_t)(nodeBase + ty * 4 + j + OFF_TR) * HID;
        uint2 hh;
        hh.x = f2h2(res[j][0] + b0, res[j][1] + b1);
        hh.y = f2h2(res[j][2] + b2, res[j][3] + b3);
        *(uint2*)(g_h0 + row + o) = hh;
    }
}

// -------- conv layer via fp16 mma.sync over node range --------
__global__ void __launch_bounds__(128) conv_mma_kernel(
        int layer, const float* __restrict__ bias, float* __restrict__ outExt,
        int nodeOffset) {
    __shared__ __half A_s[64][136];
    __shared__ __half W_s[64][136];
    const __half* __restrict__ Hroot = layer ? g_h1 : g_h0;
    const __half* __restrict__ Wh = g_wh + layer * 64 * 128;

    const int tid  = threadIdx.x;
    const int lane = tid & 31;
    const int warp = tid >> 5;
    const int nodeBase = nodeOffset + blockIdx.x * 64;

    for (int idx = tid; idx < 1024; idx += 128) {
        int n = idx >> 4, k8 = idx & 15;
        uint4 v;
        if (k8 < 8) v = *(const uint4*)(g_aggh + (size_t)(nodeBase + n) * HID + k8 * 8);
        else        v = *(const uint4*)(Hroot  + (size_t)(nodeBase + n) * HID + (k8 - 8) * 8);
        *(uint4*)&A_s[n][k8 * 8] = v;
    }
    for (int idx = tid; idx < 1024; idx += 128) {
        int o = idx >> 4, k8 = idx & 15;
        *(uint4*)&W_s[o][k8 * 8] = *(const uint4*)(Wh + o * 128 + k8 * 8);
    }
    __syncthreads();

    float c[8][4];
#pragma unroll
    for (int t8 = 0; t8 < 8; t8++)
#pragma unroll
        for (int i = 0; i < 4; i++) c[t8][i] = 0.f;

    const int row = warp * 16 + (lane >> 2);
    const int kq  = (lane & 3) * 2;
    const int nb  = lane >> 2;

#pragma unroll
    for (int s = 0; s < 8; s++) {
        int k0 = s * 16;
        unsigned a0 = *(const unsigned*)&A_s[row][k0 + kq];
        unsigned a1 = *(const unsigned*)&A_s[row + 8][k0 + kq];
        unsigned a2 = *(const unsigned*)&A_s[row][k0 + 8 + kq];
        unsigned a3 = *(const unsigned*)&A_s[row + 8][k0 + 8 + kq];
#pragma unroll
        for (int t8 = 0; t8 < 8; t8++) {
            unsigned b0 = *(const unsigned*)&W_s[t8 * 8 + nb][k0 + kq];
            unsigned b1 = *(const unsigned*)&W_s[t8 * 8 + nb][k0 + 8 + kq];
            mma_f16(c[t8], a0, a1, a2, a3, b0, b1);
        }
    }

    const int col0 = (lane & 3) * 2;
#pragma unroll
    for (int t8 = 0; t8 < 8; t8++) {
        int col = t8 * 8 + col0;
        float bc0 = bias[col], bc1 = bias[col + 1];
        float r0 = fmaxf(c[t8][0] + bc0, 0.f);
        float r1 = fmaxf(c[t8][1] + bc1, 0.f);
        float r2 = fmaxf(c[t8][2] + bc0, 0.f);
        float r3 = fmaxf(c[t8][3] + bc1, 0.f);
        size_t rA = (size_t)(nodeBase + row) * HID + col;
        size_t rB = (size_t)(nodeBase + row + 8) * HID + col;
        if (layer == 0) {
            *(unsigned*)(g_h1 + rA) = f2h2(r0, r1);
            *(unsigned*)(g_h1 + rB) = f2h2(r2, r3);
        } else {
            *(float2*)(outExt + rA) = make_float2(r0, r1);
            *(float2*)(outExt + rB) = make_float2(r2, r3);
        }
    }
}

extern "C" void kernel_launch(void* const* d_in, const int* in_sizes, int n_in,
                              void* d_out, int out_size) {
    const float* track_x   = (const float*)d_in[0];
    const int*   pl_tr_src = (const int*)d_in[1];
    const int*   pl_tr_dst = (const int*)d_in[2];
    const int*   tr_ar_src = (const int*)d_in[3];
    const int*   tr_ar_dst = (const int*)d_in[4];
    const float* pl_emb    = (const float*)d_in[5];
    const float* ar_emb    = (const float*)d_in[6];
    const float* track_W   = (const float*)d_in[7];
    const float* track_b   = (const float*)d_in[8];
    const float* type_emb  = (const float*)d_in[9];
    const float* conv_Wl   = (const float*)d_in[10];
    const float* conv_bl   = (const float*)d_in[11];
    const float* conv_Wr   = (const float*)d_in[12];
    float* out = (float*)d_out;

    const int E1 = in_sizes[1];
    const int E2 = in_sizes[3];
    const int ET = E1 + E2;
    const int H2N = NTOT - SPLIT;     // 64000

    // lazily created side stream + events
    static cudaStream_t s2 = nullptr;
    static cudaEvent_t evFork = nullptr, evB = nullptr;
    static cudaEvent_t e1 = nullptr, eC0 = nullptr, e4 = nullptr, eC1 = nullptr;
    if (s2 == nullptr) {
        cudaStreamCreateWithFlags(&s2, cudaStreamNonBlocking);
        cudaEventCreateWithFlags(&evFork, cudaEventDisableTiming);
        cudaEventCreateWithFlags(&evB, cudaEventDisableTiming);
        cudaEventCreateWithFlags(&e1, cudaEventDisableTiming);
        cudaEventCreateWithFlags(&eC0, cudaEventDisableTiming);
        cudaEventCreateWithFlags(&e4, cudaEventDisableTiming);
        cudaEventCreateWithFlags(&eC1, cudaEventDisableTiming);
    }

    cudaEventRecord(evFork, 0);
    cudaStreamWaitEvent(s2, evFork, 0);

    // launch order keeps fill_kernel at slot #4 (ncu profiles #4)
    {
        int total = (NUM_PL + NUM_AR) * (HID / 4);
        init_emb_kernel<<<(total + 255) / 256, 256>>>(pl_emb, ar_emb, type_emb);     // 1 (s0)
    }
    track_gemm_kernel<<<NUM_TR / 32, 128>>>(track_x, track_W, track_b,
                                            type_emb + HID);                         // 2 (s0)
    zero_deg_kernel<<<(NTOT + 255) / 256, 256, 0, s2>>>();                           // 3 (s2)
    fill_kernel<<<(ET / 4 + 255) / 256, 256, 0, s2>>>(pl_tr_src, pl_tr_dst, E1,
                                                      tr_ar_src, tr_ar_dst, E2);     // 4 (s2)
    wconv_kernel<<<(2 * 64 * 128 + 255) / 256, 256>>>(conv_Wl, conv_Wr);             // 5 (s0)

    cudaEventRecord(evB, s2);
    cudaStreamWaitEvent((cudaStream_t)0, evB, 0);

    // ==== layer 0 (split pipeline) ====
    gather_kernel<<<SPLIT * 16 / 256, 256>>>(0, 0, SPLIT);              // g0 H1 (s0)
    cudaEventRecord(e1, 0);
    gather_kernel<<<H2N * 16 / 256, 256>>>(0, SPLIT, H2N);              // g0 H2 (s0)
    conv_mma_kernel<<<H2N / 64, 128>>>(0, conv_bl, nullptr, SPLIT);     // c0 H2 (s0)
    cudaStreamWaitEvent(s2, e1, 0);
    conv_mma_kernel<<<SPLIT / 64, 128, 0, s2>>>(0, conv_bl, nullptr, 0);// c0 H1 (s2)
    cudaEventRecord(eC0, s2);
    cudaStreamWaitEvent((cudaStream_t)0, eC0, 0);

    // ==== layer 1 (split pipeline) ====
    gather_kernel<<<SPLIT * 16 / 256, 256>>>(1, 0, SPLIT);              // g1 H1 (s0)
    cudaEventRecord(e4, 0);
    gather_kernel<<<H2N * 16 / 256, 256>>>(1, SPLIT, H2N);              // g1 H2 (s0)
    cudaStreamWaitEvent(s2, e4, 0);
    conv_mma_kernel<<<SPLIT / 64, 128, 0, s2>>>(1, conv_bl + 64, out, 0);   // c1 H1 (s2)
    cudaEventRecord(eC1, s2);
    cudaStreamWaitEvent((cudaStream_t)0, eC1, 0);
    conv_mma_kernel<<<H2N / 64, 128>>>(1, conv_bl + 64, out, SPLIT);    // c1 H2 (s0, last)
}

// round 17
// speedup vs baseline: 1.0584x; 1.0584x over previous
#include <cuda_runtime.h>
#include <cuda_fp16.h>

#define NUM_PL 50000
#define NUM_TR 100000
#define NUM_AR 10000
#define OFF_TR NUM_PL
#define OFF_AR (NUM_PL + NUM_TR)
#define NTOT   (NUM_PL + NUM_TR + NUM_AR)
#define HID    64
#define MAXDEG 96             // fixed adjacency stride; true max deg ~70
#define SPLIT  96000          // pipeline split (divisible by 64)

typedef unsigned long long ull;

// -------- scratch (device globals; no runtime allocation) --------
// g_deg relies on: zero-initialized at load; re-zeroed at END of every launch.
__device__ __align__(16) __half g_h0  [(size_t)NTOT * HID];
__device__ __align__(16) __half g_h1  [(size_t)NTOT * HID];
__device__ __align__(16) __half g_aggh[(size_t)NTOT * HID];
__device__ __align__(16) __half g_wh  [2 * 64 * 128];
__device__ int g_deg[NTOT];
__device__ __align__(16) int g_adj[(size_t)NTOT * MAXDEG + 16]; // pad for prefetch over-read

// -------- helpers --------
__device__ __forceinline__ ull dup_f32(float x) {
    ull r; asm("mov.b64 %0, {%1,%1};" : "=l"(r) : "f"(x)); return r;
}
__device__ __forceinline__ void ffma2(ull& d, ull a, ull b) {
    asm("fma.rn.f32x2 %0, %1, %2, %3;" : "=l"(d) : "l"(a), "l"(b), "l"(d));
}
__device__ __forceinline__ float2 unpack2(ull v) {
    float2 f; asm("mov.b64 {%0,%1}, %2;" : "=f"(f.x), "=f"(f.y) : "l"(v)); return f;
}
__device__ __forceinline__ float2 h2f(unsigned u) {
    return __half22float2(*(const __half2*)&u);
}
__device__ __forceinline__ __half2 u2h(unsigned u) {
    return *(const __half2*)&u;
}
__device__ __forceinline__ unsigned f2h2(float a, float b) {
    __half2 h = __floats2half2_rn(a, b);
    return *(const unsigned*)&h;
}
__device__ __forceinline__ void mma_f16(float* c, unsigned a0, unsigned a1,
                                        unsigned a2, unsigned a3,
                                        unsigned b0, unsigned b1) {
    asm volatile("mma.sync.aligned.m16n8k16.row.col.f32.f16.f16.f32 "
                 "{%0,%1,%2,%3}, {%4,%5,%6,%7}, {%8,%9}, {%0,%1,%2,%3};"
                 : "+f"(c[0]), "+f"(c[1]), "+f"(c[2]), "+f"(c[3])
                 : "r"(a0), "r"(a1), "r"(a2), "r"(a3), "r"(b0), "r"(b1));
}

// process one 4-neighbor group (v0..v3 already loaded) into acc — HADD2 tree
__device__ __forceinline__ void acc_group(const uint4& v0, const uint4& v1,
                                          const uint4& v2, const uint4& v3,
                                          float* acc) {
#pragma unroll
    for (int q = 0; q < 4; q++) {
        __half2 sh = __hadd2(__hadd2(u2h((&v0.x)[q]), u2h((&v1.x)[q])),
                             __hadd2(u2h((&v2.x)[q]), u2h((&v3.x)[q])));
        float2 f = __half22float2(sh);
        acc[q * 2 + 0] += f.x; acc[q * 2 + 1] += f.y;
    }
}

// -------- init playlist & artist rows (fp16) --------
__global__ void init_emb_kernel(const float* __restrict__ pl_emb,
                                const float* __restrict__ ar_emb,
                                const float* __restrict__ type_emb) {
    int t = blockIdx.x * blockDim.x + threadIdx.x;
    int total = (NUM_PL + NUM_AR) * (HID / 4);
    if (t >= total) return;
    int node = t >> 4;
    int c    = (t & 15) * 4;
    const float* src; const float* ty; size_t row;
    if (node < NUM_PL) {
        src = pl_emb + (size_t)node * HID;
        row = (size_t)node * HID;
        ty  = type_emb;
    } else {
        int a = node - NUM_PL;
        src = ar_emb + (size_t)a * HID;
        row = (size_t)(OFF_AR + a) * HID;
        ty  = type_emb + 2 * HID;
    }
    float4 v  = *(const float4*)(src + c);
    float4 tv = *(const float4*)(ty  + c);
    v.x += tv.x; v.y += tv.y; v.z += tv.z; v.w += tv.w;
    uint2 h; h.x = f2h2(v.x, v.y); h.y = f2h2(v.z, v.w);
    *(uint2*)(g_h0 + row + c) = h;
}

// -------- weight pre-convert --------
__global__ void wconv_kernel(const float* __restrict__ Wl,
                             const float* __restrict__ Wr) {
    int t = blockIdx.x * blockDim.x + threadIdx.x;
    if (t >= 2 * 64 * 128) return;
    int l = t >> 13;
    int o = (t >> 7) & 63;
    int k = t & 127;
    float v = (k < 64) ? Wl[l * 64 * 64 + o * 64 + k]
                       : Wr[l * 64 * 64 + o * 64 + (k - 64)];
    g_wh[t] = __float2half_rn(v);
}

__global__ void zero_deg_kernel() {
    int i = blockIdx.x * blockDim.x + threadIdx.x;
    if (i < NTOT) g_deg[i] = 0;
}

// -------- single-pass CSR build (atomic-throughput bound; at floor) --------
__global__ void fill_kernel(const int* __restrict__ s1, const int* __restrict__ d1, int n1,
                            const int* __restrict__ s2, const int* __restrict__ d2, int n2) {
    int base = (blockIdx.x * blockDim.x + threadIdx.x) * 4;
    int total = n1 + n2;
    int aa[4], bb[4];
    int cnt = 0;
#pragma unroll
    for (int u = 0; u < 4; u++) {
        int e = base + u;
        if (e < total) {
            if (e < n1) { aa[u] = __ldg(s1 + e);               bb[u] = __ldg(d1 + e) + OFF_TR; }
            else        { aa[u] = __ldg(s2 + e - n1) + OFF_TR; bb[u] = __ldg(d2 + e - n1) + OFF_AR; }
            cnt = u + 1;
        }
    }
#pragma unroll
    for (int u = 0; u < 4; u++) {
        if (u < cnt) {
            int pa = atomicAdd(&g_deg[aa[u]], 1);
            if (pa < MAXDEG) g_adj[(size_t)aa[u] * MAXDEG + pa] = bb[u];
            int pb = atomicAdd(&g_deg[bb[u]], 1);
            if (pb < MAXDEG) g_adj[(size_t)bb[u] * MAXDEG + pb] = aa[u];
        }
    }
}

// -------- gather (r15 form): 8 lanes/node; 8-wide stage + 4-wide pipelined + tail --------
__global__ void gather_kernel(int layer, int nodeStart, int nodeCount) {
    const __half* __restrict__ H = layer ? g_h1 : g_h0;
    int t = blockIdx.x * blockDim.x + threadIdx.x;
    int nrel = t >> 3;
    if (nrel >= nodeCount) return;
    int node = nodeStart + nrel;
    int c = (t & 7) * 8;
    const int* __restrict__ adj = g_adj + (size_t)node * MAXDEG;
    int d = g_deg[node];
    if (d > MAXDEG) d = MAXDEG;
    float acc[8];
#pragma unroll
    for (int j = 0; j < 8; j++) acc[j] = 0.f;

    // s always holds adj[i..i+3] (padded array -> safe over-read)
    int4 s = *(const int4*)(adj);
    int i = 0;

    // 8-wide stage: 8 feature loads in flight
    while (i + 8 <= d) {
        int4 sa = s;
        int4 sb = *(const int4*)(adj + i + 4);
        s = *(const int4*)(adj + i + 8);           // prefetch next group
        uint4 v0 = *(const uint4*)(H + (size_t)sa.x * HID + c);
        uint4 v1 = *(const uint4*)(H + (size_t)sa.y * HID + c);
        uint4 v2 = *(const uint4*)(H + (size_t)sa.z * HID + c);
        uint4 v3 = *(const uint4*)(H + (size_t)sa.w * HID + c);
        uint4 v4 = *(const uint4*)(H + (size_t)sb.x * HID + c);
        uint4 v5 = *(const uint4*)(H + (size_t)sb.y * HID + c);
        uint4 v6 = *(const uint4*)(H + (size_t)sb.z * HID + c);
        uint4 v7 = *(const uint4*)(H + (size_t)sb.w * HID + c);
        acc_group(v0, v1, v2, v3, acc);
        acc_group(v4, v5, v6, v7, acc);
        i += 8;
    }
    // 4-wide pipelined stage
    while (i + 4 <= d) {
        int4 sn = *(const int4*)(adj + i + 4);
        uint4 v0 = *(const uint4*)(H + (size_t)s.x * HID + c);
        uint4 v1 = *(const uint4*)(H + (size_t)s.y * HID + c);
        uint4 v2 = *(const uint4*)(H + (size_t)s.z * HID + c);
        uint4 v3 = *(const uint4*)(H + (size_t)s.w * HID + c);
        acc_group(v0, v1, v2, v3, acc);
        s = sn;
        i += 4;
    }
    // tail (0..3): neighbors already in s
    int r = d - i;
    if (r > 0) {
        uint4 v = *(const uint4*)(H + (size_t)s.x * HID + c);
#pragma unroll
        for (int q = 0; q < 4; q++) {
            float2 f = h2f((&v.x)[q]);
            acc[q * 2 + 0] += f.x; acc[q * 2 + 1] += f.y;
        }
    }
    if (r > 1) {
        uint4 v = *(const uint4*)(H + (size_t)s.y * HID + c);
#pragma unroll
        for (int q = 0; q < 4; q++) {
            float2 f = h2f((&v.x)[q]);
            acc[q * 2 + 0] += f.x; acc[q * 2 + 1] += f.y;
        }
    }
    if (r > 2) {
        uint4 v = *(const uint4*)(H + (size_t)s.z * HID + c);
#pragma unroll
        for (int q = 0; q < 4; q++) {
            float2 f = h2f((&v.x)[q]);
            acc[q * 2 + 0] += f.x; acc[q * 2 + 1] += f.y;
        }
    }

    float rd = 1.0f / (float)(d > 0 ? d : 1);
    uint4 hv;
    hv.x = f2h2(acc[0] * rd, acc[1] * rd);
    hv.y = f2h2(acc[2] * rd, acc[3] * rd);
    hv.z = f2h2(acc[4] * rd, acc[5] * rd);
    hv.w = f2h2(acc[6] * rd, acc[7] * rd);
    *(uint4*)(g_aggh + (size_t)node * HID + c) = hv;
}

// -------- track GEMM (exact f32x2) --------
__global__ void __launch_bounds__(128) track_gemm_kernel(
        const float* __restrict__ A, const float* __restrict__ W,
        const float* __restrict__ bias, const float* __restrict__ bias2) {
    __shared__ float Ws[64][68];
    __shared__ float rows[128][36];
    const int tid = threadIdx.x;
    const int tx  = tid & 15;
    const int ty  = tid >> 4;
    const int nodeBase = blockIdx.x * 32;

    for (int it = 0; it < 32; it++)
        rows[tid][it] = A[(size_t)(nodeBase + it) * 128 + tid];

    ull a01[4], a23[4];
#pragma unroll
    for (int i = 0; i < 4; i++) { a01[i] = 0ull; a23[i] = 0ull; }

    for (int h = 0; h < 2; h++) {
        __syncthreads();
        for (int idx = tid; idx < 64 * 64; idx += 128) {
            int o = idx >> 6, k = idx & 63;
            Ws[k][o] = W[(size_t)o * 128 + h * 64 + k];
        }
        __syncthreads();
#pragma unroll 8
        for (int k = 0; k < 64; k++) {
            ulonglong2 rp = *(const ulonglong2*)&rows[(h << 6) + k][ty * 4];
            float4 w = *(const float4*)&Ws[k][tx * 4];
            ull w0 = dup_f32(w.x), w1 = dup_f32(w.y);
            ull w2 = dup_f32(w.z), w3 = dup_f32(w.w);
            ffma2(a01[0], rp.x, w0); ffma2(a23[0], rp.y, w0);
            ffma2(a01[1], rp.x, w1); ffma2(a23[1], rp.y, w1);
            ffma2(a01[2], rp.x, w2); ffma2(a23[2], rp.y, w2);
            ffma2(a01[3], rp.x, w3); ffma2(a23[3], rp.y, w3);
        }
    }

    const int o = tx * 4;
    float b0 = bias[o] + bias2[o],         b1 = bias[o + 1] + bias2[o + 1];
    float b2 = bias[o + 2] + bias2[o + 2], b3 = bias[o + 3] + bias2[o + 3];
    float res[4][4];
#pragma unroll
    for (int i = 0; i < 4; i++) {
        float2 p = unpack2(a01[i]);
        float2 q = unpack2(a23[i]);
        res[0][i] = p.x; res[1][i] = p.y; res[2][i] = q.x; res[3][i] = q.y;
    }
#pragma unroll
    for (int j = 0; j < 4; j++) {
        size_t row = (size_t)(nodeBase + ty * 4 + j + OFF_TR) * HID;
        uint2 hh;
        hh.x = f2h2(res[j][0] + b0, res[j][1] + b1);
        hh.y = f2h2(res[j][2] + b2, res[j][3] + b3);
        *(uint2*)(g_h0 + row + o) = hh;
    }
}

// -------- conv layer via fp16 mma.sync over node range --------
__global__ void __launch_bounds__(128) conv_mma_kernel(
        int layer, const float* __restrict__ bias, float* __restrict__ outExt,
        int nodeOffset) {
    __shared__ __half A_s[64][136];
    __shared__ __half W_s[64][136];
    const __half* __restrict__ Hroot = layer ? g_h1 : g_h0;
    const __half* __restrict__ Wh = g_wh + layer * 64 * 128;

    const int tid  = threadIdx.x;
    const int lane = tid & 31;
    const int warp = tid >> 5;
    const int nodeBase = nodeOffset + blockIdx.x * 64;

    for (int idx = tid; idx < 1024; idx += 128) {
        int n = idx >> 4, k8 = idx & 15;
        uint4 v;
        if (k8 < 8) v = *(const uint4*)(g_aggh + (size_t)(nodeBase + n) * HID + k8 * 8);
        else        v = *(const uint4*)(Hroot  + (size_t)(nodeBase + n) * HID + (k8 - 8) * 8);
        *(uint4*)&A_s[n][k8 * 8] = v;
    }
    for (int idx = tid; idx < 1024; idx += 128) {
        int o = idx >> 4, k8 = idx & 15;
        *(uint4*)&W_s[o][k8 * 8] = *(const uint4*)(Wh + o * 128 + k8 * 8);
    }
    __syncthreads();

    float c[8][4];
#pragma unroll
    for (int t8 = 0; t8 < 8; t8++)
#pragma unroll
        for (int i = 0; i < 4; i++) c[t8][i] = 0.f;

    const int row = warp * 16 + (lane >> 2);
    const int kq  = (lane & 3) * 2;
    const int nb  = lane >> 2;

#pragma unroll
    for (int s = 0; s < 8; s++) {
        int k0 = s * 16;
        unsigned a0 = *(const unsigned*)&A_s[row][k0 + kq];
        unsigned a1 = *(const unsigned*)&A_s[row + 8][k0 + kq];
        unsigned a2 = *(const unsigned*)&A_s[row][k0 + 8 + kq];
        unsigned a3 = *(const unsigned*)&A_s[row + 8][k0 + 8 + kq];
#pragma unroll
        for (int t8 = 0; t8 < 8; t8++) {
            unsigned b0 = *(const unsigned*)&W_s[t8 * 8 + nb][k0 + kq];
            unsigned b1 = *(const unsigned*)&W_s[t8 * 8 + nb][k0 + 8 + kq];
            mma_f16(c[t8], a0, a1, a2, a3, b0, b1);
        }
    }

    const int col0 = (lane & 3) * 2;
#pragma unroll
    for (int t8 = 0; t8 < 8; t8++) {
        int col = t8 * 8 + col0;
        float bc0 = bias[col], bc1 = bias[col + 1];
        float r0 = fmaxf(c[t8][0] + bc0, 0.f);
        float r1 = fmaxf(c[t8][1] + bc1, 0.f);
        float r2 = fmaxf(c[t8][2] + bc0, 0.f);
        float r3 = fmaxf(c[t8][3] + bc1, 0.f);
        size_t rA = (size_t)(nodeBase + row) * HID + col;
        size_t rB = (size_t)(nodeBase + row + 8) * HID + col;
        if (layer == 0) {
            *(unsigned*)(g_h1 + rA) = f2h2(r0, r1);
            *(unsigned*)(g_h1 + rB) = f2h2(r2, r3);
        } else {
            *(float2*)(outExt + rA) = make_float2(r0, r1);
            *(float2*)(outExt + rB) = make_float2(r2, r3);
        }
    }
}

extern "C" void kernel_launch(void* const* d_in, const int* in_sizes, int n_in,
                              void* d_out, int out_size) {
    const float* track_x   = (const float*)d_in[0];
    const int*   pl_tr_src = (const int*)d_in[1];
    const int*   pl_tr_dst = (const int*)d_in[2];
    const int*   tr_ar_src = (const int*)d_in[3];
    const int*   tr_ar_dst = (const int*)d_in[4];
    const float* pl_emb    = (const float*)d_in[5];
    const float* ar_emb    = (const float*)d_in[6];
    const float* track_W   = (const float*)d_in[7];
    const float* track_b   = (const float*)d_in[8];
    const float* type_emb  = (const float*)d_in[9];
    const float* conv_Wl   = (const float*)d_in[10];
    const float* conv_bl   = (const float*)d_in[11];
    const float* conv_Wr   = (const float*)d_in[12];
    float* out = (float*)d_out;

    const int E1 = in_sizes[1];
    const int E2 = in_sizes[3];
    const int ET = E1 + E2;
    const int H2N = NTOT - SPLIT;     // 64000

    // lazily created side stream + events
    static cudaStream_t s2 = nullptr;
    static cudaEvent_t evFork = nullptr, evB = nullptr;
    static cudaEvent_t e1 = nullptr, eC0 = nullptr, e4 = nullptr;
    static cudaEvent_t eG1 = nullptr, eEnd = nullptr;
    if (s2 == nullptr) {
        cudaStreamCreateWithFlags(&s2, cudaStreamNonBlocking);
        cudaEventCreateWithFlags(&evFork, cudaEventDisableTiming);
        cudaEventCreateWithFlags(&evB, cudaEventDisableTiming);
        cudaEventCreateWithFlags(&e1, cudaEventDisableTiming);
        cudaEventCreateWithFlags(&eC0, cudaEventDisableTiming);
        cudaEventCreateWithFlags(&e4, cudaEventDisableTiming);
        cudaEventCreateWithFlags(&eG1, cudaEventDisableTiming);
        cudaEventCreateWithFlags(&eEnd, cudaEventDisableTiming);
    }

    cudaEventRecord(evFork, 0);
    cudaStreamWaitEvent(s2, evFork, 0);

    // NOTE: g_deg is zero at entry (zeroed at END of previous launch; zero-init at load).
    // launch order keeps fill_kernel at slot #3 on s2 (front-critical, profiled earlier)
    {
        int total = (NUM_PL + NUM_AR) * (HID / 4);
        init_emb_kernel<<<(total + 255) / 256, 256>>>(pl_emb, ar_emb, type_emb);     // s0
    }
    track_gemm_kernel<<<NUM_TR / 32, 128>>>(track_x, track_W, track_b,
                                            type_emb + HID);                         // s0
    fill_kernel<<<(ET / 4 + 255) / 256, 256, 0, s2>>>(pl_tr_src, pl_tr_dst, E1,
                                                      tr_ar_src, tr_ar_dst, E2);     // s2
    wconv_kernel<<<(2 * 64 * 128 + 255) / 256, 256>>>(conv_Wl, conv_Wr);             // s0

    cudaEventRecord(evB, s2);
    cudaStreamWaitEvent((cudaStream_t)0, evB, 0);

    // ==== layer 0 (split pipeline) ====
    gather_kernel<<<SPLIT * 8 / 256, 256>>>(0, 0, SPLIT);               // g0 H1 (s0)
    cudaEventRecord(e1, 0);
    gather_kernel<<<H2N * 8 / 256, 256>>>(0, SPLIT, H2N);               // g0 H2 (s0)
    conv_mma_kernel<<<H2N / 64, 128>>>(0, conv_bl, nullptr, SPLIT);     // c0 H2 (s0)
    cudaStreamWaitEvent(s2, e1, 0);
    conv_mma_kernel<<<SPLIT / 64, 128, 0, s2>>>(0, conv_bl, nullptr, 0);// c0 H1 (s2)
    cudaEventRecord(eC0, s2);
    cudaStreamWaitEvent((cudaStream_t)0, eC0, 0);

    // ==== layer 1 (split pipeline; c1 H2 NOT serialized behind c1 H1) ====
    gather_kernel<<<SPLIT * 8 / 256, 256>>>(1, 0, SPLIT);               // g1 H1 (s0)
    cudaEventRecord(e4, 0);
    gather_kernel<<<H2N * 8 / 256, 256>>>(1, SPLIT, H2N);               // g1 H2 (s0)
    cudaEventRecord(eG1, 0);                                            // all gathers done
    conv_mma_kernel<<<H2N / 64, 128>>>(1, conv_bl + 64, out, SPLIT);    // c1 H2 (s0)
    cudaStreamWaitEvent(s2, e4, 0);
    conv_mma_kernel<<<SPLIT / 64, 128, 0, s2>>>(1, conv_bl + 64, out, 0);   // c1 H1 (s2)
    // zero g_deg for the NEXT launch, concurrent with the convs (g_deg's last
    // reader is g1 H2, guarded by eG1)
    cudaStreamWaitEvent(s2, eG1, 0);
    zero_deg_kernel<<<(NTOT + 255) / 256, 256, 0, s2>>>();              // s2
    cudaEventRecord(eEnd, s2);
    cudaStreamWaitEvent((cudaStream_t)0, eEnd, 0);                      // join
}